// round 15
// baseline (speedup 1.0000x reference)
#include <cuda_runtime.h>
#include <cuda_bf16.h>
#include <math.h>
#include <stdint.h>

#define DMODEL 2048
#define NHEADS 16
#define HDIM   128
#define BATCH  2
#define SEQ    2048
#define MROWS  (BATCH*SEQ)            // 4096
#define BHS    (BATCH*NHEADS*SEQ)     // 65536

typedef unsigned long long u64t;

// ---------------- generic-PTX tensor core / async helpers -------------------
__device__ __forceinline__ uint32_t smem_u32(const void* p) {
    uint32_t a;
    asm("{ .reg .u64 t; cvta.to.shared.u64 t, %1; cvt.u32.u64 %0, t; }"
        : "=r"(a) : "l"(p));
    return a;
}
__device__ __forceinline__ void ldm_x4(uint32_t r[4], uint32_t addr) {
    asm volatile("ldmatrix.sync.aligned.m8n8.x4.shared.b16 {%0,%1,%2,%3}, [%4];"
        : "=r"(r[0]), "=r"(r[1]), "=r"(r[2]), "=r"(r[3]) : "r"(addr));
}
__device__ __forceinline__ void ldm_x2(uint32_t r[2], uint32_t addr) {
    asm volatile("ldmatrix.sync.aligned.m8n8.x2.shared.b16 {%0,%1}, [%2];"
        : "=r"(r[0]), "=r"(r[1]) : "r"(addr));
}
__device__ __forceinline__ void ldm_x2t(uint32_t r[2], uint32_t addr) {
    asm volatile("ldmatrix.sync.aligned.m8n8.x2.trans.shared.b16 {%0,%1}, [%2];"
        : "=r"(r[0]), "=r"(r[1]) : "r"(addr));
}
__device__ __forceinline__ void mma_bf16(float c[4], const uint32_t a[4],
                                         const uint32_t b[2]) {
    asm volatile(
        "mma.sync.aligned.m16n8k16.row.col.f32.bf16.bf16.f32 "
        "{%0,%1,%2,%3}, {%4,%5,%6,%7}, {%8,%9}, {%0,%1,%2,%3};"
        : "+f"(c[0]), "+f"(c[1]), "+f"(c[2]), "+f"(c[3])
        : "r"(a[0]), "r"(a[1]), "r"(a[2]), "r"(a[3]), "r"(b[0]), "r"(b[1]));
}
__device__ __forceinline__ void mma_s8(int c[4], const uint32_t a[4],
                                       const uint32_t b[2]) {
    asm volatile(
        "mma.sync.aligned.m16n8k32.row.col.s32.s8.s8.s32 "
        "{%0,%1,%2,%3}, {%4,%5,%6,%7}, {%8,%9}, {%0,%1,%2,%3};"
        : "+r"(c[0]), "+r"(c[1]), "+r"(c[2]), "+r"(c[3])
        : "r"(a[0]), "r"(a[1]), "r"(a[2]), "r"(a[3]), "r"(b[0]), "r"(b[1]));
}
__device__ __forceinline__ void cpa16(uint32_t dst, const void* src) {
    asm volatile("cp.async.ca.shared.global [%0], [%1], 16;"
                 :: "r"(dst), "l"(src) : "memory");
}
#define CP_COMMIT() asm volatile("cp.async.commit_group;" ::: "memory")
#define CP_WAIT1()  asm volatile("cp.async.wait_group 1;" ::: "memory")
#define CP_WAIT0()  asm volatile("cp.async.wait_group 0;" ::: "memory")

__device__ __forceinline__ uint32_t pack_bf16(float a, float b) {
    __nv_bfloat16 ha = __float2bfloat16_rn(a), hb = __float2bfloat16_rn(b);
    return (uint32_t)__bfloat16_as_ushort(ha)
         | ((uint32_t)__bfloat16_as_ushort(hb) << 16);
}

// ---------------- scratch ----------------------------------------------------
__device__ float g_q[BHS*HDIM];
__device__ float g_k[BHS*HDIM];
__device__ float g_att[MROWS*DMODEL];
__device__ float g_cos[SEQ*64];
__device__ float g_sin[SEQ*64];
// int8 two-digit operands + per-row scales (ss = rowmax/16256)
__device__ __align__(16) char qx0[MROWS*DMODEL],  qx1[MROWS*DMODEL];
__device__ __align__(16) char qw0[4*DMODEL*DMODEL], qw1[4*DMODEL*DMODEL];
__device__ __align__(16) char qa0[MROWS*DMODEL],  qa1[MROWS*DMODEL];
__device__ float g_ssx[MROWS];
__device__ float g_ssw[4*DMODEL];
__device__ float g_ssa[MROWS];
// bf16 attention operands
__device__ __align__(16) __nv_bfloat16 gqh[BHS*HDIM], gql[BHS*HDIM];
__device__ __align__(16) __nv_bfloat16 gkh[BHS*HDIM], gkl[BHS*HDIM];
__device__ __align__(16) __nv_bfloat16 gvh[BHS*HDIM], gvl[BHS*HDIM];

// ---------------- RoPE table -------------------------------------------------
__global__ void rope_table_kernel() {
    int idx = blockIdx.x * 256 + threadIdx.x;
    if (idx >= SEQ * 64) return;
    int s = idx >> 6, p = idx & 63;
    double invf = pow(10000.0, -((double)(2 * p)) / 128.0);
    float invf_f = (float)invf;
    float ang = (float)s * invf_f;
    g_cos[idx] = (float)cos((double)ang);
    g_sin[idx] = (float)sin((double)ang);
}

// ---------------- fp32 -> int8 two-digit row quantization --------------------
// mode 0: 12288 rows (x:4096, then w0..w3: 2048 each); mode 1: g_att 4096 rows
__global__ __launch_bounds__(256) void quant_kernel(
        const float* __restrict__ x,  const float* __restrict__ w0,
        const float* __restrict__ w1, const float* __restrict__ w2,
        const float* __restrict__ w3, int mode) {
    int row  = blockIdx.x * 8 + (threadIdx.x >> 5);
    int lane = threadIdx.x & 31;
    const float* src;
    char *d0p, *d1p;
    float* sp;
    if (mode == 1) {
        src = g_att + (size_t)row * DMODEL;
        d0p = qa0 + (size_t)row * DMODEL;
        d1p = qa1 + (size_t)row * DMODEL;
        sp  = g_ssa + row;
    } else if (row < MROWS) {
        src = x + (size_t)row * DMODEL;
        d0p = qx0 + (size_t)row * DMODEL;
        d1p = qx1 + (size_t)row * DMODEL;
        sp  = g_ssx + row;
    } else {
        int k = row - MROWS;
        int slab = k >> 11, wr = k & 2047;
        const float* W = (slab == 0) ? w0 : (slab == 1) ? w1
                        : (slab == 2) ? w2 : w3;
        src = W + (size_t)wr * DMODEL;
        size_t off = ((size_t)slab * DMODEL + wr) * DMODEL;
        d0p = qw0 + off; d1p = qw1 + off;
        sp  = g_ssw + slab * DMODEL + wr;
    }

    float m = 0.f;
#pragma unroll
    for (int it = 0; it < 16; ++it) {
        float4 v = *(const float4*)(src + it * 128 + lane * 4);
        m = fmaxf(m, fmaxf(fmaxf(fabsf(v.x), fabsf(v.y)),
                           fmaxf(fabsf(v.z), fabsf(v.w))));
    }
#pragma unroll
    for (int s = 16; s; s >>= 1) m = fmaxf(m, __shfl_xor_sync(~0u, m, s));
    float scl = fmaxf(m, 1e-30f);
    float inv = 16256.f / scl;
    if (lane == 0) *sp = scl * (1.f / 16256.f);

#pragma unroll
    for (int it = 0; it < 16; ++it) {
        float4 v = *(const float4*)(src + it * 128 + lane * 4);
        float xf[4] = {v.x, v.y, v.z, v.w};
        uint32_t u0 = 0, u1 = 0;
#pragma unroll
        for (int q = 0; q < 4; ++q) {
            float X  = rintf(xf[q] * inv);
            float f0 = rintf(X * (1.f / 128.f));
            int   i0 = (int)f0;
            int   i1 = (int)(X - 128.f * f0);
            u0 |= ((uint32_t)(uint8_t)(char)i0) << (8 * q);
            u1 |= ((uint32_t)(uint8_t)(char)i1) << (8 * q);
        }
        *(uint32_t*)(d0p + it * 128 + lane * 4) = u0;
        *(uint32_t*)(d1p + it * 128 + lane * 4) = u1;
    }
}

// ---------------- int8 GEMM: 128x128 tile, KC=64, dual int32 accum -----------
#define KC 64
#define NCHUNK (DMODEL/KC)      // 32
#define ROWB 80                 // bytes per smem row (64 + 16 pad)
#define SARR (128*ROWB)         // 10240
#define SBUF (4*SARR)           // 40960
#define GSMEM (2*SBUF)          // 81920

__global__ __launch_bounds__(256) void gemm_s8(float* __restrict__ Cout,
                                               int mode) {
    extern __shared__ __align__(16) char smc[];
    const uint32_t smb = smem_u32(smc);
    const int tid = threadIdx.x;
    const int lane = tid & 31, wid = tid >> 5;
    const int warpM = (wid >> 2) * 64;
    const int warpN = (wid & 3) * 32;

    const int m0  = blockIdx.y * 128;
    const int n0g = blockIdx.x * 128;
    const int slab = (mode == 0) ? (n0g >> 11) : 3;
    const int n0   = (mode == 0) ? (n0g & 2047) : n0g;

    const char* A0 = (mode == 0) ? qx0 : qa0;
    const char* A1 = (mode == 0) ? qx1 : qa1;
    const char* B0 = qw0 + (size_t)slab * DMODEL * DMODEL;
    const char* B1 = qw1 + (size_t)slab * DMODEL * DMODEL;
    const float* SSA = (mode == 0) ? g_ssx : g_ssa;
    const float* SSB = g_ssw + slab * DMODEL;

    // per chunk: 4 arrays x 128 rows x 4 segs(16B) = 2048 cp.async, 8/thread
#define LOAD_CHUNK(c, buf) do {                                                \
    const int c0 = (c) * KC;                                                   \
    const uint32_t bb = smb + (buf) * SBUF;                                    \
    _Pragma("unroll")                                                          \
    for (int i = 0; i < 8; ++i) {                                              \
        int idx = tid + 256 * i;                                               \
        int arr = idx >> 9, rem = idx & 511;                                   \
        int r = rem >> 2, seg = rem & 3;                                       \
        uint32_t d = (uint32_t)(arr * SARR + r * ROWB + seg * 16);             \
        const char* base =                                                     \
            (arr == 0) ? A0 : (arr == 1) ? A1 : (arr == 2) ? B0 : B1;          \
        int row0 = (arr < 2) ? m0 : n0;                                        \
        cpa16(bb + d, base + (size_t)(row0 + r) * DMODEL + c0 + seg * 16);     \
    } } while (0)

    LOAD_CHUNK(0, 0); CP_COMMIT();
    LOAD_CHUNK(1, 1); CP_COMMIT();

    int acc0[4][4][4], accx[4][4][4];
#pragma unroll
    for (int mt = 0; mt < 4; ++mt)
#pragma unroll
        for (int nt = 0; nt < 4; ++nt)
#pragma unroll
            for (int q = 0; q < 4; ++q) { acc0[mt][nt][q] = 0; accx[mt][nt][q] = 0; }

    const uint32_t aoff = (uint32_t)((warpM + (lane & 15)) * ROWB
                                     + (lane >> 4) * 16);
    const uint32_t boff = (uint32_t)((warpN + (lane & 7)) * ROWB
                                     + ((lane >> 3) & 1) * 16);

    for (int c = 0; c < NCHUNK; ++c) {
        const int buf = c & 1;
        if (c + 2 < NCHUNK) CP_WAIT1(); else CP_WAIT0();
        __syncthreads();

        const uint32_t bA0 = smb + buf * SBUF + 0 * SARR;
        const uint32_t bA1 = smb + buf * SBUF + 1 * SARR;
        const uint32_t bB0 = smb + buf * SBUF + 2 * SARR;
        const uint32_t bB1 = smb + buf * SBUF + 3 * SARR;

#pragma unroll
        for (int ks = 0; ks < 2; ++ks) {
            const uint32_t kb = ks * 32;
            uint32_t ah[4][4], al[4][4], bh[4][2], bl[4][2];
#pragma unroll
            for (int mt = 0; mt < 4; ++mt) {
                uint32_t o = aoff + (uint32_t)(mt * 16 * ROWB) + kb;
                ldm_x4(ah[mt], bA0 + o);
                ldm_x4(al[mt], bA1 + o);
            }
#pragma unroll
            for (int nt = 0; nt < 4; ++nt) {
                uint32_t o = boff + (uint32_t)(nt * 8 * ROWB) + kb;
                ldm_x2(bh[nt], bB0 + o);
                ldm_x2(bl[nt], bB1 + o);
            }
#pragma unroll
            for (int mt = 0; mt < 4; ++mt)
#pragma unroll
                for (int nt = 0; nt < 4; ++nt)
                    mma_s8(acc0[mt][nt], ah[mt], bh[nt]);
#pragma unroll
            for (int mt = 0; mt < 4; ++mt)
#pragma unroll
                for (int nt = 0; nt < 4; ++nt)
                    mma_s8(accx[mt][nt], ah[mt], bl[nt]);
#pragma unroll
            for (int mt = 0; mt < 4; ++mt)
#pragma unroll
                for (int nt = 0; nt < 4; ++nt)
                    mma_s8(accx[mt][nt], al[mt], bh[nt]);
        }
        __syncthreads();
        if (c + 2 < NCHUNK) { LOAD_CHUNK(c + 2, buf); CP_COMMIT(); }
    }

    const int hh = (n0g & 2047) >> 7;
#pragma unroll
    for (int mt = 0; mt < 4; ++mt) {
#pragma unroll
        for (int nt = 0; nt < 4; ++nt) {
            int rA = m0 + warpM + mt * 16 + (lane >> 2);
            int cc = warpN + nt * 8 + (lane & 3) * 2;
            float sb0 = SSB[((mode == 0) ? n0 : n0g) + cc];
            float sb1 = SSB[((mode == 0) ? n0 : n0g) + cc + 1];
#pragma unroll
            for (int half = 0; half < 2; ++half) {
                int r = rA + half * 8;
                float sa = SSA[r];
                float f0 = 16384.f * (float)acc0[mt][nt][half * 2]
                         + 128.f * (float)accx[mt][nt][half * 2];
                float f1 = 16384.f * (float)acc0[mt][nt][half * 2 + 1]
                         + 128.f * (float)accx[mt][nt][half * 2 + 1];
                float2 val = make_float2(sa * sb0 * f0, sa * sb1 * f1);
                if (mode == 0) {
                    int b = r >> 11, s = r & 2047;
                    size_t ix = (((size_t)b * NHEADS + hh) * SEQ + s) * HDIM + cc;
                    if (slab == 2) {
                        __nv_bfloat16 h0 = __float2bfloat16_rn(val.x);
                        __nv_bfloat16 h1 = __float2bfloat16_rn(val.y);
                        *(uint32_t*)&gvh[ix] =
                            (uint32_t)__bfloat16_as_ushort(h0)
                          | ((uint32_t)__bfloat16_as_ushort(h1) << 16);
                        *(uint32_t*)&gvl[ix] = pack_bf16(
                            val.x - __bfloat162float(h0),
                            val.y - __bfloat162float(h1));
                    } else {
                        float* OUT = (slab == 0) ? g_q : g_k;
                        *(float2*)(OUT + ix) = val;
                    }
                } else {
                    *(float2*)(Cout + (size_t)r * DMODEL + n0g + cc) = val;
                }
            }
        }
    }
}

// ---------------- fused RoPE + per-head LayerNorm -> bf16 hi/lo split --------
__global__ __launch_bounds__(128) void rope_ln_kernel(const float* __restrict__ qw,
                                                      const float* __restrict__ kw) {
    int row  = blockIdx.x * 4 + (threadIdx.x >> 5);
    int lane = threadIdx.x & 31;
    bool is_q = (row < BHS);
    int r2 = is_q ? row : row - BHS;
    const float* base = is_q ? g_q : g_k;
    const float* w = is_q ? qw : kw;
    int s = r2 & (SEQ - 1);

    const float* ptr = base + (size_t)r2 * HDIM + lane * 4;
    float4 v = *(const float4*)ptr;
    int p0 = lane * 2, p1 = lane * 2 + 1;
    float c0 = g_cos[s * 64 + p0], s0 = g_sin[s * 64 + p0];
    float c1 = g_cos[s * 64 + p1], s1 = g_sin[s * 64 + p1];
    float o0 = v.x * c0 - v.y * s0;
    float o1 = v.x * s0 + v.y * c0;
    float o2 = v.z * c1 - v.w * s1;
    float o3 = v.z * s1 + v.w * c1;

    float sum = o0 + o1 + o2 + o3;
#pragma unroll
    for (int m = 16; m; m >>= 1) sum += __shfl_xor_sync(~0u, sum, m);
    float mu = sum * (1.0f / 128.0f);
    float d0 = o0 - mu, d1 = o1 - mu, d2 = o2 - mu, d3 = o3 - mu;
    float ss = d0 * d0 + d1 * d1 + d2 * d2 + d3 * d3;
#pragma unroll
    for (int m = 16; m; m >>= 1) ss += __shfl_xor_sync(~0u, ss, m);
    float rstd = rsqrtf(ss * (1.0f / 128.0f) + 1e-5f);
    float scl = is_q ? 0.08838834764831845f : 1.0f;
    rstd *= scl;

    float4 wv = *(const float4*)(w + lane * 4);
    float r0 = d0 * rstd * wv.x, r1 = d1 * rstd * wv.y;
    float r2f = d2 * rstd * wv.z, r3 = d3 * rstd * wv.w;

    __nv_bfloat16* dh = is_q ? gqh : gkh;
    __nv_bfloat16* dl = is_q ? gql : gkl;
    size_t ix = (size_t)r2 * HDIM + lane * 4;
    __nv_bfloat16 h0 = __float2bfloat16_rn(r0), h1 = __float2bfloat16_rn(r1);
    __nv_bfloat16 h2 = __float2bfloat16_rn(r2f), h3 = __float2bfloat16_rn(r3);
    *(uint2*)&dh[ix] = make_uint2(
        (uint32_t)__bfloat16_as_ushort(h0) | ((uint32_t)__bfloat16_as_ushort(h1) << 16),
        (uint32_t)__bfloat16_as_ushort(h2) | ((uint32_t)__bfloat16_as_ushort(h3) << 16));
    *(uint2*)&dl[ix] = make_uint2(
        pack_bf16(r0 - __bfloat162float(h0), r1 - __bfloat162float(h1)),
        pack_bf16(r2f - __bfloat162float(h2), r3 - __bfloat162float(h3)));
}

// ---------------- mma.sync flash attention (R11 core, fp32 epilogue) ---------
#define QSTRB 272
#define KVBUF 69632
#define OQH 0
#define OQL 34816
#define OKV0 69632
#define ATTN_SMEM (69632*3)
#define NEGBIG (-1e9f)

__global__ __launch_bounds__(256) void attn_kernel(const int* __restrict__ wptr) {
    extern __shared__ __align__(16) char smc[];
    const uint32_t smb = smem_u32(smc);
    const int tid = threadIdx.x;
    const int lane = tid & 31, wid = tid >> 5;
    const int bh = blockIdx.x;
    const int q0 = blockIdx.y * 128;
    const int W  = *wptr;

    const size_t hb = (size_t)bh * SEQ * HDIM;
    const __nv_bfloat16 *qh = gqh + hb, *ql = gql + hb;
    const __nv_bfloat16 *kh = gkh + hb, *kl = gkl + hb;
    const __nv_bfloat16 *vh = gvh + hb, *vl = gvl + hb;

    int t0 = q0 - W; if (t0 < 0) t0 = 0; t0 &= ~63;
    const int ntiles = (q0 + 64 - t0) / 64 + 1;

#define LOAD_KV(t, buf) do {                                                   \
    const int kt_ = t0 + 64 * (t);                                             \
    const uint32_t kb_ = smb + OKV0 + (buf) * KVBUF;                           \
    _Pragma("unroll")                                                          \
    for (int i = 0; i < 16; ++i) {                                             \
        int idx = tid + 256 * i;                                               \
        int arr = idx >> 10, rem = idx & 1023;                                 \
        int r = rem >> 4, seg = rem & 15;                                      \
        const __nv_bfloat16* src =                                             \
            (arr == 0) ? kh : (arr == 1) ? kl : (arr == 2) ? vh : vl;          \
        cpa16(kb_ + arr * 17408 + r * QSTRB + seg * 16,                        \
              src + (size_t)(kt_ + r) * HDIM + seg * 8);                       \
    } } while (0)

#pragma unroll
    for (int i = 0; i < 8; ++i) {
        int idx = tid + 256 * i;
        int r = idx >> 4, seg = idx & 15;
        cpa16(smb + OQH + r * QSTRB + seg * 16,
              qh + (size_t)(q0 + r) * HDIM + seg * 8);
        cpa16(smb + OQL + r * QSTRB + seg * 16,
              ql + (size_t)(q0 + r) * HDIM + seg * 8);
    }
    LOAD_KV(0, 0); CP_COMMIT();
    if (ntiles > 1) { LOAD_KV(1, 1); CP_COMMIT(); }

    float o[16][4];
#pragma unroll
    for (int v = 0; v < 16; ++v)
#pragma unroll
        for (int q = 0; q < 4; ++q) o[v][q] = 0.f;
    float mrow0 = NEGBIG, mrow1 = NEGBIG, l0 = 0.f, l1 = 0.f;

    const int R0 = q0 + 16 * wid + (lane >> 2);
    const int R1 = R0 + 8;

    for (int t = 0; t < ntiles; ++t) {
        const int kt = t0 + 64 * t;
        const uint32_t kvb = smb + OKV0 + (t & 1) * KVBUF;
        if (t + 1 < ntiles) CP_WAIT1(); else CP_WAIT0();
        __syncthreads();

        float sc[8][4];
#pragma unroll
        for (int j = 0; j < 8; ++j)
#pragma unroll
            for (int q = 0; q < 4; ++q) sc[j][q] = 0.f;

        const uint32_t aoffQ = (16 * wid + (lane & 15)) * QSTRB
                             + (lane >> 4) * 16;
#pragma unroll
        for (int ks = 0; ks < 8; ++ks) {
            uint32_t ah4[4], al4[4];
            ldm_x4(ah4, smb + OQH + aoffQ + 32 * ks);
            ldm_x4(al4, smb + OQL + aoffQ + 32 * ks);
#pragma unroll
            for (int j = 0; j < 8; ++j) {
                uint32_t kb = (8 * j + (lane & 7)) * QSTRB
                            + ((lane >> 3) & 1) * 16 + 32 * ks;
                uint32_t bh2[2], bl2[2];
                ldm_x2(bh2, kvb + kb);
                ldm_x2(bl2, kvb + 17408 + kb);
                mma_bf16(sc[j], ah4, bh2);
                mma_bf16(sc[j], ah4, bl2);
                mma_bf16(sc[j], al4, bh2);
            }
        }

        float mx0 = NEGBIG, mx1 = NEGBIG;
#pragma unroll
        for (int j = 0; j < 8; ++j) {
            int kg = kt + 8 * j + 2 * (lane & 3);
            if (!(kg   <= R0 && kg   >= R0 - W)) sc[j][0] = NEGBIG;
            if (!(kg+1 <= R0 && kg+1 >= R0 - W)) sc[j][1] = NEGBIG;
            if (!(kg   <= R1 && kg   >= R1 - W)) sc[j][2] = NEGBIG;
            if (!(kg+1 <= R1 && kg+1 >= R1 - W)) sc[j][3] = NEGBIG;
            mx0 = fmaxf(mx0, fmaxf(sc[j][0], sc[j][1]));
            mx1 = fmaxf(mx1, fmaxf(sc[j][2], sc[j][3]));
        }
        mx0 = fmaxf(mx0, __shfl_xor_sync(~0u, mx0, 1));
        mx0 = fmaxf(mx0, __shfl_xor_sync(~0u, mx0, 2));
        mx1 = fmaxf(mx1, __shfl_xor_sync(~0u, mx1, 1));
        mx1 = fmaxf(mx1, __shfl_xor_sync(~0u, mx1, 2));

        float mn0 = fmaxf(mrow0, mx0), mn1 = fmaxf(mrow1, mx1);
        float a0 = __expf(fminf(mrow0 - mn0, 0.f));
        float a1 = __expf(fminf(mrow1 - mn1, 0.f));
        mrow0 = mn0; mrow1 = mn1;
        l0 *= a0; l1 *= a1;
#pragma unroll
        for (int v = 0; v < 16; ++v) {
            o[v][0] *= a0; o[v][1] *= a0; o[v][2] *= a1; o[v][3] *= a1;
        }

        uint32_t ph[4][4], pl[4][4];
#pragma unroll
        for (int j = 0; j < 8; ++j) {
            int kg = kt + 8 * j + 2 * (lane & 3);
            bool v0 = (kg   <= R0 && kg   >= R0 - W);
            bool v1 = (kg+1 <= R0 && kg+1 >= R0 - W);
            bool v2 = (kg   <= R1 && kg   >= R1 - W);
            bool v3 = (kg+1 <= R1 && kg+1 >= R1 - W);
            float p0 = v0 ? __expf(fminf(sc[j][0] - mn0, 0.f)) : 0.f;
            float p1 = v1 ? __expf(fminf(sc[j][1] - mn0, 0.f)) : 0.f;
            float p2 = v2 ? __expf(fminf(sc[j][2] - mn1, 0.f)) : 0.f;
            float p3 = v3 ? __expf(fminf(sc[j][3] - mn1, 0.f)) : 0.f;
            l0 += p0 + p1; l1 += p2 + p3;
            __nv_bfloat16 h0 = __float2bfloat16_rn(p0);
            __nv_bfloat16 h1 = __float2bfloat16_rn(p1);
            __nv_bfloat16 h2 = __float2bfloat16_rn(p2);
            __nv_bfloat16 h3 = __float2bfloat16_rn(p3);
            int ks2 = j >> 1, hf = (j & 1) * 2;
            ph[ks2][hf + 0] = (uint32_t)__bfloat16_as_ushort(h0)
                            | ((uint32_t)__bfloat16_as_ushort(h1) << 16);
            ph[ks2][hf + 1] = (uint32_t)__bfloat16_as_ushort(h2)
                            | ((uint32_t)__bfloat16_as_ushort(h3) << 16);
            pl[ks2][hf + 0] = pack_bf16(p0 - __bfloat162float(h0),
                                        p1 - __bfloat162float(h1));
            pl[ks2][hf + 1] = pack_bf16(p2 - __bfloat162float(h2),
                                        p3 - __bfloat162float(h3));
        }

#pragma unroll
        for (int ks2 = 0; ks2 < 4; ++ks2) {
#pragma unroll
            for (int v = 0; v < 16; ++v) {
                uint32_t vb = (16 * ks2 + (lane & 15)) * QSTRB + 16 * v;
                uint32_t vh2[2], vl2[2];
                ldm_x2t(vh2, kvb + 34816 + vb);
                ldm_x2t(vl2, kvb + 52224 + vb);
                mma_bf16(o[v], ph[ks2], vh2);
                mma_bf16(o[v], ph[ks2], vl2);
                mma_bf16(o[v], pl[ks2], vh2);
            }
        }
        __syncthreads();
        if (t + 2 < ntiles) { LOAD_KV(t + 2, t & 1); CP_COMMIT(); }
    }

    l0 += __shfl_xor_sync(~0u, l0, 1); l0 += __shfl_xor_sync(~0u, l0, 2);
    l1 += __shfl_xor_sync(~0u, l1, 1); l1 += __shfl_xor_sync(~0u, l1, 2);
    float inv0 = 1.0f / fmaxf(l0, 1e-30f);
    float inv1 = 1.0f / fmaxf(l1, 1e-30f);

    const int b = bh >> 4, h = bh & 15;
    const size_t rb0 = ((size_t)(b * SEQ + R0)) * DMODEL + h * HDIM;
    const size_t rb1 = ((size_t)(b * SEQ + R1)) * DMODEL + h * HDIM;
#pragma unroll
    for (int v = 0; v < 16; ++v) {
        int c = 8 * v + 2 * (lane & 3);
        *(float2*)(g_att + rb0 + c) = make_float2(o[v][0] * inv0, o[v][1] * inv0);
        *(float2*)(g_att + rb1 + c) = make_float2(o[v][2] * inv1, o[v][3] * inv1);
    }
}

// ---------------- launch -----------------------------------------------------
extern "C" void kernel_launch(void* const* d_in, const int* in_sizes, int n_in,
                              void* d_out, int out_size) {
    const float* x   = (const float*)d_in[0];
    const float* wq  = (const float*)d_in[1];
    const float* wk  = (const float*)d_in[2];
    const float* wv  = (const float*)d_in[3];
    const float* wo  = (const float*)d_in[4];
    const float* qnw = (const float*)d_in[5];
    const float* knw = (const float*)d_in[6];
    const int*   wsz = (const int*)d_in[7];
    (void)in_sizes; (void)n_in; (void)out_size;

    cudaFuncSetAttribute(gemm_s8,
                         cudaFuncAttributeMaxDynamicSharedMemorySize, GSMEM);
    cudaFuncSetAttribute(attn_kernel,
                         cudaFuncAttributeMaxDynamicSharedMemorySize, ATTN_SMEM);

    rope_table_kernel<<<(SEQ * 64 + 255) / 256, 256>>>();
    quant_kernel<<<(MROWS + 4 * DMODEL) / 8, 256>>>(x, wq, wk, wv, wo, 0);

    gemm_s8<<<dim3(3 * DMODEL / 128, MROWS / 128), 256, GSMEM>>>(nullptr, 0);
    rope_ln_kernel<<<(2 * BHS) / 4, 128>>>(qnw, knw);
    attn_kernel<<<dim3(BATCH * NHEADS, SEQ / 128), 256, ATTN_SMEM>>>(wsz);
    quant_kernel<<<MROWS / 8, 256>>>(x, wq, wk, wv, wo, 1);
    gemm_s8<<<dim3(DMODEL / 128, MROWS / 128), 256, GSMEM>>>((float*)d_out, 1);
}

// round 16
// speedup vs baseline: 2.3618x; 2.3618x over previous
#include <cuda_runtime.h>
#include <cuda_bf16.h>
#include <math.h>
#include <stdint.h>

#define DMODEL 2048
#define NHEADS 16
#define HDIM   128
#define BATCH  2
#define SEQ    2048
#define MROWS  (BATCH*SEQ)            // 4096
#define BHS    (BATCH*NHEADS*SEQ)     // 65536

typedef unsigned long long u64t;

// ---------------- generic-PTX tensor core / async helpers -------------------
__device__ __forceinline__ uint32_t smem_u32(const void* p) {
    uint32_t a;
    asm("{ .reg .u64 t; cvta.to.shared.u64 t, %1; cvt.u32.u64 %0, t; }"
        : "=r"(a) : "l"(p));
    return a;
}
__device__ __forceinline__ void ldm_x4(uint32_t r[4], uint32_t addr) {
    asm volatile("ldmatrix.sync.aligned.m8n8.x4.shared.b16 {%0,%1,%2,%3}, [%4];"
        : "=r"(r[0]), "=r"(r[1]), "=r"(r[2]), "=r"(r[3]) : "r"(addr));
}
__device__ __forceinline__ void ldm_x2(uint32_t r[2], uint32_t addr) {
    asm volatile("ldmatrix.sync.aligned.m8n8.x2.shared.b16 {%0,%1}, [%2];"
        : "=r"(r[0]), "=r"(r[1]) : "r"(addr));
}
__device__ __forceinline__ void ldm_x2t(uint32_t r[2], uint32_t addr) {
    asm volatile("ldmatrix.sync.aligned.m8n8.x2.trans.shared.b16 {%0,%1}, [%2];"
        : "=r"(r[0]), "=r"(r[1]) : "r"(addr));
}
__device__ __forceinline__ void mma_bf16(float c[4], const uint32_t a[4],
                                         const uint32_t b[2]) {
    asm volatile(
        "mma.sync.aligned.m16n8k16.row.col.f32.bf16.bf16.f32 "
        "{%0,%1,%2,%3}, {%4,%5,%6,%7}, {%8,%9}, {%0,%1,%2,%3};"
        : "+f"(c[0]), "+f"(c[1]), "+f"(c[2]), "+f"(c[3])
        : "r"(a[0]), "r"(a[1]), "r"(a[2]), "r"(a[3]), "r"(b[0]), "r"(b[1]));
}
__device__ __forceinline__ void cpa16(uint32_t dst, const void* src) {
    asm volatile("cp.async.ca.shared.global [%0], [%1], 16;"
                 :: "r"(dst), "l"(src) : "memory");
}
#define CP_COMMIT() asm volatile("cp.async.commit_group;" ::: "memory")
#define CP_WAIT1()  asm volatile("cp.async.wait_group 1;" ::: "memory")
#define CP_WAIT0()  asm volatile("cp.async.wait_group 0;" ::: "memory")

__device__ __forceinline__ uint32_t pack_bf16(float a, float b) {
    __nv_bfloat16 ha = __float2bfloat16_rn(a), hb = __float2bfloat16_rn(b);
    return (uint32_t)__bfloat16_as_ushort(ha)
         | ((uint32_t)__bfloat16_as_ushort(hb) << 16);
}

// ---------------- scratch ----------------------------------------------------
__device__ float g_q[BHS*HDIM];
__device__ float g_k[BHS*HDIM];
__device__ float g_cos[SEQ*64];
__device__ float g_sin[SEQ*64];
__device__ __align__(16) __nv_bfloat16 gxh[MROWS*DMODEL],  gxl[MROWS*DMODEL];
__device__ __align__(16) __nv_bfloat16 gwh[4*DMODEL*DMODEL], gwl[4*DMODEL*DMODEL];
__device__ __align__(16) __nv_bfloat16 gatth[MROWS*DMODEL], gattl[MROWS*DMODEL];
__device__ __align__(16) __nv_bfloat16 gqh[BHS*HDIM], gql[BHS*HDIM];
__device__ __align__(16) __nv_bfloat16 gkh[BHS*HDIM], gkl[BHS*HDIM];
__device__ __align__(16) __nv_bfloat16 gvh[BHS*HDIM], gvl[BHS*HDIM];

// ---------------- RoPE table -------------------------------------------------
__global__ void rope_table_kernel() {
    int idx = blockIdx.x * 256 + threadIdx.x;
    if (idx >= SEQ * 64) return;
    int s = idx >> 6, p = idx & 63;
    double invf = pow(10000.0, -((double)(2 * p)) / 128.0);
    float invf_f = (float)invf;
    float ang = (float)s * invf_f;
    g_cos[idx] = (float)cos((double)ang);
    g_sin[idx] = (float)sin((double)ang);
}

// ---------------- fused fp32 -> bf16 hi/lo split (single launch) -------------
#define N4X (MROWS*DMODEL/4)
#define N4W (DMODEL*DMODEL/4)
#define N4TOT (N4X + 4*N4W)

__global__ __launch_bounds__(256) void split_all_kernel(
        const float* __restrict__ x,  const float* __restrict__ w0,
        const float* __restrict__ w1, const float* __restrict__ w2,
        const float* __restrict__ w3) {
    int i = blockIdx.x * 256 + threadIdx.x;
    if (i >= N4TOT) return;
    const float* src;
    __nv_bfloat16 *dh, *dl;
    size_t j;
    if (i < N4X) { src = x; dh = gxh; dl = gxl; j = i; }
    else {
        int k = i - N4X;
        int slab = k / N4W;
        j = k - slab * N4W;
        src = (slab == 0) ? w0 : (slab == 1) ? w1 : (slab == 2) ? w2 : w3;
        size_t off = (size_t)slab * DMODEL * DMODEL;
        dh = gwh + off; dl = gwl + off;
    }
    float4 f = ((const float4*)src)[j];
    __nv_bfloat16 h0 = __float2bfloat16_rn(f.x), h1 = __float2bfloat16_rn(f.y);
    __nv_bfloat16 h2 = __float2bfloat16_rn(f.z), h3 = __float2bfloat16_rn(f.w);
    uint2 uh = make_uint2(
        (uint32_t)__bfloat16_as_ushort(h0) | ((uint32_t)__bfloat16_as_ushort(h1) << 16),
        (uint32_t)__bfloat16_as_ushort(h2) | ((uint32_t)__bfloat16_as_ushort(h3) << 16));
    uint2 ul = make_uint2(
        pack_bf16(f.x - __bfloat162float(h0), f.y - __bfloat162float(h1)),
        pack_bf16(f.z - __bfloat162float(h2), f.w - __bfloat162float(h3)));
    *(uint2*)(dh + 4 * j) = uh;
    *(uint2*)(dl + 4 * j) = ul;
}

// ---------------- bf16 GEMM (R11/R14 proven config) --------------------------
#define KC 32
#define NCHUNK (DMODEL/KC)
#define ASTR 40
#define SARR (128*ASTR*2)
#define SBUF (4*SARR)
#define GSMEM (2*SBUF)          // 81920

__global__ __launch_bounds__(256) void gemm_bf16(float* __restrict__ Cout,
                                                 int mode) {
    extern __shared__ __align__(16) char smc[];
    const uint32_t smb = smem_u32(smc);
    const int tid = threadIdx.x;
    const int lane = tid & 31, wid = tid >> 5;
    const int warpM = (wid >> 2) * 64;
    const int warpN = (wid & 3) * 32;

    const int m0  = blockIdx.y * 128;
    const int n0g = blockIdx.x * 128;
    const int slab = (mode == 0) ? (n0g >> 11) : 3;
    const int n0   = (mode == 0) ? (n0g & 2047) : n0g;

    const __nv_bfloat16* Ah = (mode == 0) ? gxh : gatth;
    const __nv_bfloat16* Al = (mode == 0) ? gxl : gattl;
    const __nv_bfloat16* Bh = gwh + (size_t)slab * DMODEL * DMODEL;
    const __nv_bfloat16* Bl = gwl + (size_t)slab * DMODEL * DMODEL;

#define LOAD_CHUNK(c, buf) do {                                                \
    const int c0 = (c) * KC;                                                   \
    const uint32_t bb = smb + (buf) * SBUF;                                    \
    _Pragma("unroll")                                                          \
    for (int i = 0; i < 2; ++i) {                                              \
        int idx = tid + 256 * i;                                               \
        int r = idx >> 2, seg = idx & 3;                                       \
        uint32_t d = r * (ASTR * 2) + seg * 16;                                \
        size_t sa = (size_t)(m0 + r) * DMODEL + c0 + seg * 8;                  \
        size_t sb = (size_t)(n0 + r) * DMODEL + c0 + seg * 8;                  \
        cpa16(bb + 0 * SARR + d, Ah + sa);                                     \
        cpa16(bb + 1 * SARR + d, Al + sa);                                     \
        cpa16(bb + 2 * SARR + d, Bh + sb);                                     \
        cpa16(bb + 3 * SARR + d, Bl + sb);                                     \
    } } while (0)

    LOAD_CHUNK(0, 0); CP_COMMIT();
    LOAD_CHUNK(1, 1); CP_COMMIT();

    float acc[4][4][4];
#pragma unroll
    for (int mt = 0; mt < 4; ++mt)
#pragma unroll
        for (int nt = 0; nt < 4; ++nt)
#pragma unroll
            for (int q = 0; q < 4; ++q) acc[mt][nt][q] = 0.f;

    const uint32_t aoff = (uint32_t)(((warpM + (lane & 15)) * ASTR
                                      + (lane >> 4) * 8) * 2);
    const uint32_t boff = (uint32_t)(((warpN + (lane & 7)) * ASTR
                                      + ((lane >> 3) & 1) * 8) * 2);

    for (int c = 0; c < NCHUNK; ++c) {
        const int buf = c & 1;
        if (c + 2 < NCHUNK) CP_WAIT1(); else CP_WAIT0();
        __syncthreads();

        const uint32_t bA_h = smb + buf * SBUF + 0 * SARR;
        const uint32_t bA_l = smb + buf * SBUF + 1 * SARR;
        const uint32_t bB_h = smb + buf * SBUF + 2 * SARR;
        const uint32_t bB_l = smb + buf * SBUF + 3 * SARR;

#pragma unroll
        for (int ks = 0; ks < 2; ++ks) {
            const uint32_t kb = ks * 32;
            uint32_t ah[4][4], al[4][4], bh[4][2], bl[4][2];
#pragma unroll
            for (int mt = 0; mt < 4; ++mt) {
                uint32_t o = aoff + (uint32_t)(mt * 16 * ASTR * 2) + kb;
                ldm_x4(ah[mt], bA_h + o);
                ldm_x4(al[mt], bA_l + o);
            }
#pragma unroll
            for (int nt = 0; nt < 4; ++nt) {
                uint32_t o = boff + (uint32_t)(nt * 8 * ASTR * 2) + kb;
                ldm_x2(bh[nt], bB_h + o);
                ldm_x2(bl[nt], bB_l + o);
            }
#pragma unroll
            for (int mt = 0; mt < 4; ++mt)
#pragma unroll
                for (int nt = 0; nt < 4; ++nt)
                    mma_bf16(acc[mt][nt], ah[mt], bh[nt]);
#pragma unroll
            for (int mt = 0; mt < 4; ++mt)
#pragma unroll
                for (int nt = 0; nt < 4; ++nt)
                    mma_bf16(acc[mt][nt], ah[mt], bl[nt]);
#pragma unroll
            for (int mt = 0; mt < 4; ++mt)
#pragma unroll
                for (int nt = 0; nt < 4; ++nt)
                    mma_bf16(acc[mt][nt], al[mt], bh[nt]);
        }
        __syncthreads();
        if (c + 2 < NCHUNK) { LOAD_CHUNK(c + 2, buf); CP_COMMIT(); }
    }

    const int hh = (n0g & 2047) >> 7;
#pragma unroll
    for (int mt = 0; mt < 4; ++mt) {
#pragma unroll
        for (int nt = 0; nt < 4; ++nt) {
            int rA = m0 + warpM + mt * 16 + (lane >> 2);
            int cc = warpN + nt * 8 + (lane & 3) * 2;
#pragma unroll
            for (int half = 0; half < 2; ++half) {
                int r = rA + half * 8;
                float2 val = make_float2(acc[mt][nt][half * 2],
                                         acc[mt][nt][half * 2 + 1]);
                if (mode == 0) {
                    int b = r >> 11, s = r & 2047;
                    size_t ix = (((size_t)b * NHEADS + hh) * SEQ + s) * HDIM + cc;
                    if (slab == 2) {
                        __nv_bfloat16 h0 = __float2bfloat16_rn(val.x);
                        __nv_bfloat16 h1 = __float2bfloat16_rn(val.y);
                        *(uint32_t*)&gvh[ix] =
                            (uint32_t)__bfloat16_as_ushort(h0)
                          | ((uint32_t)__bfloat16_as_ushort(h1) << 16);
                        *(uint32_t*)&gvl[ix] = pack_bf16(
                            val.x - __bfloat162float(h0),
                            val.y - __bfloat162float(h1));
                    } else {
                        float* OUT = (slab == 0) ? g_q : g_k;
                        *(float2*)(OUT + ix) = val;
                    }
                } else {
                    *(float2*)(Cout + (size_t)r * DMODEL + n0g + cc) = val;
                }
            }
        }
    }
}

// ---------------- fused RoPE + per-head LayerNorm -> bf16 hi/lo split --------
__global__ __launch_bounds__(128) void rope_ln_kernel(const float* __restrict__ qw,
                                                      const float* __restrict__ kw) {
    int row  = blockIdx.x * 4 + (threadIdx.x >> 5);
    int lane = threadIdx.x & 31;
    bool is_q = (row < BHS);
    int r2 = is_q ? row : row - BHS;
    const float* base = is_q ? g_q : g_k;
    const float* w = is_q ? qw : kw;
    int s = r2 & (SEQ - 1);

    const float* ptr = base + (size_t)r2 * HDIM + lane * 4;
    float4 v = *(const float4*)ptr;
    int p0 = lane * 2, p1 = lane * 2 + 1;
    float c0 = g_cos[s * 64 + p0], s0 = g_sin[s * 64 + p0];
    float c1 = g_cos[s * 64 + p1], s1 = g_sin[s * 64 + p1];
    float o0 = v.x * c0 - v.y * s0;
    float o1 = v.x * s0 + v.y * c0;
    float o2 = v.z * c1 - v.w * s1;
    float o3 = v.z * s1 + v.w * c1;

    float sum = o0 + o1 + o2 + o3;
#pragma unroll
    for (int m = 16; m; m >>= 1) sum += __shfl_xor_sync(~0u, sum, m);
    float mu = sum * (1.0f / 128.0f);
    float d0 = o0 - mu, d1 = o1 - mu, d2 = o2 - mu, d3 = o3 - mu;
    float ss = d0 * d0 + d1 * d1 + d2 * d2 + d3 * d3;
#pragma unroll
    for (int m = 16; m; m >>= 1) ss += __shfl_xor_sync(~0u, ss, m);
    float rstd = rsqrtf(ss * (1.0f / 128.0f) + 1e-5f);
    float scl = is_q ? 0.08838834764831845f : 1.0f;
    rstd *= scl;

    float4 wv = *(const float4*)(w + lane * 4);
    float r0 = d0 * rstd * wv.x, r1 = d1 * rstd * wv.y;
    float r2f = d2 * rstd * wv.z, r3 = d3 * rstd * wv.w;

    __nv_bfloat16* dh = is_q ? gqh : gkh;
    __nv_bfloat16* dl = is_q ? gql : gkl;
    size_t ix = (size_t)r2 * HDIM + lane * 4;
    __nv_bfloat16 h0 = __float2bfloat16_rn(r0), h1 = __float2bfloat16_rn(r1);
    __nv_bfloat16 h2 = __float2bfloat16_rn(r2f), h3 = __float2bfloat16_rn(r3);
    *(uint2*)&dh[ix] = make_uint2(
        (uint32_t)__bfloat16_as_ushort(h0) | ((uint32_t)__bfloat16_as_ushort(h1) << 16),
        (uint32_t)__bfloat16_as_ushort(h2) | ((uint32_t)__bfloat16_as_ushort(h3) << 16));
    *(uint2*)&dl[ix] = make_uint2(
        pack_bf16(r0 - __bfloat162float(h0), r1 - __bfloat162float(h1)),
        pack_bf16(r2f - __bfloat162float(h2), r3 - __bfloat162float(h3)));
}

// ---------------- mma.sync flash attention (R11 core, LPT q-tile order) ------
#define QSTRB 272
#define KVBUF 69632
#define OQH 0
#define OQL 34816
#define OKV0 69632
#define ATTN_SMEM (69632*3)
#define NEGBIG (-1e9f)

__global__ __launch_bounds__(256) void attn_kernel(const int* __restrict__ wptr) {
    extern __shared__ __align__(16) char smc[];
    const uint32_t smb = smem_u32(smc);
    const int tid = threadIdx.x;
    const int lane = tid & 31, wid = tid >> 5;
    const int bh = blockIdx.x;
    // LPT: largest q-tiles (most KV tiles) launch first
    const int q0 = (gridDim.y - 1 - blockIdx.y) * 128;
    const int W  = *wptr;

    const size_t hb = (size_t)bh * SEQ * HDIM;
    const __nv_bfloat16 *qh = gqh + hb, *ql = gql + hb;
    const __nv_bfloat16 *kh = gkh + hb, *kl = gkl + hb;
    const __nv_bfloat16 *vh = gvh + hb, *vl = gvl + hb;

    int t0 = q0 - W; if (t0 < 0) t0 = 0; t0 &= ~63;
    const int ntiles = (q0 + 64 - t0) / 64 + 1;

#define LOAD_KV(t, buf) do {                                                   \
    const int kt_ = t0 + 64 * (t);                                             \
    const uint32_t kb_ = smb + OKV0 + (buf) * KVBUF;                           \
    _Pragma("unroll")                                                          \
    for (int i = 0; i < 16; ++i) {                                             \
        int idx = tid + 256 * i;                                               \
        int arr = idx >> 10, rem = idx & 1023;                                 \
        int r = rem >> 4, seg = rem & 15;                                      \
        const __nv_bfloat16* src =                                             \
            (arr == 0) ? kh : (arr == 1) ? kl : (arr == 2) ? vh : vl;          \
        cpa16(kb_ + arr * 17408 + r * QSTRB + seg * 16,                        \
              src + (size_t)(kt_ + r) * HDIM + seg * 8);                       \
    } } while (0)

#pragma unroll
    for (int i = 0; i < 8; ++i) {
        int idx = tid + 256 * i;
        int r = idx >> 4, seg = idx & 15;
        cpa16(smb + OQH + r * QSTRB + seg * 16,
              qh + (size_t)(q0 + r) * HDIM + seg * 8);
        cpa16(smb + OQL + r * QSTRB + seg * 16,
              ql + (size_t)(q0 + r) * HDIM + seg * 8);
    }
    LOAD_KV(0, 0); CP_COMMIT();
    if (ntiles > 1) { LOAD_KV(1, 1); CP_COMMIT(); }

    float o[16][4];
#pragma unroll
    for (int v = 0; v < 16; ++v)
#pragma unroll
        for (int q = 0; q < 4; ++q) o[v][q] = 0.f;
    float mrow0 = NEGBIG, mrow1 = NEGBIG, l0 = 0.f, l1 = 0.f;

    const int R0 = q0 + 16 * wid + (lane >> 2);
    const int R1 = R0 + 8;

    for (int t = 0; t < ntiles; ++t) {
        const int kt = t0 + 64 * t;
        const uint32_t kvb = smb + OKV0 + (t & 1) * KVBUF;
        if (t + 1 < ntiles) CP_WAIT1(); else CP_WAIT0();
        __syncthreads();

        float sc[8][4];
#pragma unroll
        for (int j = 0; j < 8; ++j)
#pragma unroll
            for (int q = 0; q < 4; ++q) sc[j][q] = 0.f;

        const uint32_t aoffQ = (16 * wid + (lane & 15)) * QSTRB
                             + (lane >> 4) * 16;
#pragma unroll
        for (int ks = 0; ks < 8; ++ks) {
            uint32_t ah4[4], al4[4];
            ldm_x4(ah4, smb + OQH + aoffQ + 32 * ks);
            ldm_x4(al4, smb + OQL + aoffQ + 32 * ks);
#pragma unroll
            for (int j = 0; j < 8; ++j) {
                uint32_t kb = (8 * j + (lane & 7)) * QSTRB
                            + ((lane >> 3) & 1) * 16 + 32 * ks;
                uint32_t bh2[2], bl2[2];
                ldm_x2(bh2, kvb + kb);
                ldm_x2(bl2, kvb + 17408 + kb);
                mma_bf16(sc[j], ah4, bh2);
                mma_bf16(sc[j], ah4, bl2);
                mma_bf16(sc[j], al4, bh2);
            }
        }

        float mx0 = NEGBIG, mx1 = NEGBIG;
#pragma unroll
        for (int j = 0; j < 8; ++j) {
            int kg = kt + 8 * j + 2 * (lane & 3);
            if (!(kg   <= R0 && kg   >= R0 - W)) sc[j][0] = NEGBIG;
            if (!(kg+1 <= R0 && kg+1 >= R0 - W)) sc[j][1] = NEGBIG;
            if (!(kg   <= R1 && kg   >= R1 - W)) sc[j][2] = NEGBIG;
            if (!(kg+1 <= R1 && kg+1 >= R1 - W)) sc[j][3] = NEGBIG;
            mx0 = fmaxf(mx0, fmaxf(sc[j][0], sc[j][1]));
            mx1 = fmaxf(mx1, fmaxf(sc[j][2], sc[j][3]));
        }
        mx0 = fmaxf(mx0, __shfl_xor_sync(~0u, mx0, 1));
        mx0 = fmaxf(mx0, __shfl_xor_sync(~0u, mx0, 2));
        mx1 = fmaxf(mx1, __shfl_xor_sync(~0u, mx1, 1));
        mx1 = fmaxf(mx1, __shfl_xor_sync(~0u, mx1, 2));

        float mn0 = fmaxf(mrow0, mx0), mn1 = fmaxf(mrow1, mx1);
        float a0 = __expf(fminf(mrow0 - mn0, 0.f));
        float a1 = __expf(fminf(mrow1 - mn1, 0.f));
        mrow0 = mn0; mrow1 = mn1;
        l0 *= a0; l1 *= a1;
#pragma unroll
        for (int v = 0; v < 16; ++v) {
            o[v][0] *= a0; o[v][1] *= a0; o[v][2] *= a1; o[v][3] *= a1;
        }

        uint32_t ph[4][4], pl[4][4];
#pragma unroll
        for (int j = 0; j < 8; ++j) {
            int kg = kt + 8 * j + 2 * (lane & 3);
            bool v0 = (kg   <= R0 && kg   >= R0 - W);
            bool v1 = (kg+1 <= R0 && kg+1 >= R0 - W);
            bool v2 = (kg   <= R1 && kg   >= R1 - W);
            bool v3 = (kg+1 <= R1 && kg+1 >= R1 - W);
            float p0 = v0 ? __expf(fminf(sc[j][0] - mn0, 0.f)) : 0.f;
            float p1 = v1 ? __expf(fminf(sc[j][1] - mn0, 0.f)) : 0.f;
            float p2 = v2 ? __expf(fminf(sc[j][2] - mn1, 0.f)) : 0.f;
            float p3 = v3 ? __expf(fminf(sc[j][3] - mn1, 0.f)) : 0.f;
            l0 += p0 + p1; l1 += p2 + p3;
            __nv_bfloat16 h0 = __float2bfloat16_rn(p0);
            __nv_bfloat16 h1 = __float2bfloat16_rn(p1);
            __nv_bfloat16 h2 = __float2bfloat16_rn(p2);
            __nv_bfloat16 h3 = __float2bfloat16_rn(p3);
            int ks2 = j >> 1, hf = (j & 1) * 2;
            ph[ks2][hf + 0] = (uint32_t)__bfloat16_as_ushort(h0)
                            | ((uint32_t)__bfloat16_as_ushort(h1) << 16);
            ph[ks2][hf + 1] = (uint32_t)__bfloat16_as_ushort(h2)
                            | ((uint32_t)__bfloat16_as_ushort(h3) << 16);
            pl[ks2][hf + 0] = pack_bf16(p0 - __bfloat162float(h0),
                                        p1 - __bfloat162float(h1));
            pl[ks2][hf + 1] = pack_bf16(p2 - __bfloat162float(h2),
                                        p3 - __bfloat162float(h3));
        }

#pragma unroll
        for (int ks2 = 0; ks2 < 4; ++ks2) {
#pragma unroll
            for (int v = 0; v < 16; ++v) {
                uint32_t vb = (16 * ks2 + (lane & 15)) * QSTRB + 16 * v;
                uint32_t vh2[2], vl2[2];
                ldm_x2t(vh2, kvb + 34816 + vb);
                ldm_x2t(vl2, kvb + 52224 + vb);
                mma_bf16(o[v], ph[ks2], vh2);
                mma_bf16(o[v], ph[ks2], vl2);
                mma_bf16(o[v], pl[ks2], vh2);
            }
        }
        __syncthreads();
        if (t + 2 < ntiles) { LOAD_KV(t + 2, t & 1); CP_COMMIT(); }
    }

    l0 += __shfl_xor_sync(~0u, l0, 1); l0 += __shfl_xor_sync(~0u, l0, 2);
    l1 += __shfl_xor_sync(~0u, l1, 1); l1 += __shfl_xor_sync(~0u, l1, 2);
    float inv0 = 1.0f / fmaxf(l0, 1e-30f);
    float inv1 = 1.0f / fmaxf(l1, 1e-30f);

    const int b = bh >> 4, h = bh & 15;
    const size_t rb0 = ((size_t)(b * SEQ + R0)) * DMODEL + h * HDIM;
    const size_t rb1 = ((size_t)(b * SEQ + R1)) * DMODEL + h * HDIM;
#pragma unroll
    for (int v = 0; v < 16; ++v) {
        int c = 8 * v + 2 * (lane & 3);
        float x0 = o[v][0] * inv0, x1 = o[v][1] * inv0;
        float x2 = o[v][2] * inv1, x3 = o[v][3] * inv1;
        __nv_bfloat16 h0 = __float2bfloat16_rn(x0);
        __nv_bfloat16 h1 = __float2bfloat16_rn(x1);
        __nv_bfloat16 h2 = __float2bfloat16_rn(x2);
        __nv_bfloat16 h3 = __float2bfloat16_rn(x3);
        *(uint32_t*)&gatth[rb0 + c] =
            (uint32_t)__bfloat16_as_ushort(h0)
          | ((uint32_t)__bfloat16_as_ushort(h1) << 16);
        *(uint32_t*)&gatth[rb1 + c] =
            (uint32_t)__bfloat16_as_ushort(h2)
          | ((uint32_t)__bfloat16_as_ushort(h3) << 16);
        *(uint32_t*)&gattl[rb0 + c] =
            pack_bf16(x0 - __bfloat162float(h0), x1 - __bfloat162float(h1));
        *(uint32_t*)&gattl[rb1 + c] =
            pack_bf16(x2 - __bfloat162float(h2), x3 - __bfloat162float(h3));
    }
}

// ---------------- launch -----------------------------------------------------
extern "C" void kernel_launch(void* const* d_in, const int* in_sizes, int n_in,
                              void* d_out, int out_size) {
    const float* x   = (const float*)d_in[0];
    const float* wq  = (const float*)d_in[1];
    const float* wk  = (const float*)d_in[2];
    const float* wv  = (const float*)d_in[3];
    const float* wo  = (const float*)d_in[4];
    const float* qnw = (const float*)d_in[5];
    const float* knw = (const float*)d_in[6];
    const int*   wsz = (const int*)d_in[7];
    (void)in_sizes; (void)n_in; (void)out_size;

    cudaFuncSetAttribute(gemm_bf16,
                         cudaFuncAttributeMaxDynamicSharedMemorySize, GSMEM);
    cudaFuncSetAttribute(attn_kernel,
                         cudaFuncAttributeMaxDynamicSharedMemorySize, ATTN_SMEM);

    rope_table_kernel<<<(SEQ * 64 + 255) / 256, 256>>>();
    split_all_kernel<<<(N4TOT + 255) / 256, 256>>>(x, wq, wk, wv, wo);

    gemm_bf16<<<dim3(3 * DMODEL / 128, MROWS / 128), 256, GSMEM>>>(nullptr, 0);
    rope_ln_kernel<<<(2 * BHS) / 4, 128>>>(qnw, knw);
    attn_kernel<<<dim3(BATCH * NHEADS, SEQ / 128), 256, ATTN_SMEM>>>(wsz);
    gemm_bf16<<<dim3(DMODEL / 128, MROWS / 128), 256, GSMEM>>>((float*)d_out, 1);
}